// round 7
// baseline (speedup 1.0000x reference)
#include <cuda_runtime.h>

// Problem constants
#define TS   1000
#define BTOT 2048
#define HE   64     // encoder hidden
#define HD   65     // decoder hidden
#define GE   256    // 4*HE
#define NB   7      // batch elements per block
#define NB1  4      // group 1: batches 0..3
#define NGRID 296   // 2 CTAs per SM on 148 SMs
#define NTH  128    // threads per block
#define HSTR 68     // h row stride (16B-aligned rows)
#define GD   260    // 4*HD

typedef unsigned long long u64;

__device__ __forceinline__ u64 pack2(float lo, float hi){
    u64 r; asm("mov.b64 %0, {%1, %2};" : "=l"(r) : "f"(lo), "f"(hi)); return r;
}
__device__ __forceinline__ float2 unpk(u64 v){
    float2 f; asm("mov.b64 {%0, %1}, %2;" : "=f"(f.x), "=f"(f.y) : "l"(v)); return f;
}
__device__ __forceinline__ u64 ffma2(u64 a, u64 b, u64 c){
    u64 d; asm("fma.rn.f32x2 %0, %1, %2, %3;" : "=l"(d) : "l"(a), "l"(b), "l"(c)); return d;
}
// accurate sigmoid (recurrent path: i, f gates)
__device__ __forceinline__ float sigf(float x){
    return __fdividef(1.0f, 1.0f + __expf(-x));
}
// accurate tanh (recurrent path: g gate)
__device__ __forceinline__ float tanhf_(float x){
    return fmaf(2.0f, sigf(2.0f * x), -1.0f);
}
// fast tanh via MUFU.TANH (non-recurrent path only)
__device__ __forceinline__ float tanha(float x){
    float y; asm("tanh.approx.f32 %0, %1;" : "=f"(y) : "f"(x)); return y;
}
// fast sigmoid via MUFU.TANH (o gate only)
__device__ __forceinline__ float siga(float x){
    return fmaf(0.5f, tanha(0.5f * x), 0.5f);
}

// one LSTM activation item: reads 4 gates from g_s row bb, updates c, writes h
#define ACT_STEP(bb, uu, cvar, H) { \
    float ig_ = g_s[bb][uu]; \
    float fg_ = g_s[bb][(H) + (uu)]; \
    float gg_ = g_s[bb][2*(H) + (uu)]; \
    float og_ = g_s[bb][3*(H) + (uu)]; \
    float cc_ = sigf(fg_) * (cvar) + sigf(ig_) * tanhf_(gg_); \
    (cvar) = cc_; \
    h_s[bb][uu] = siga(og_) * tanha(cc_); }

// encoder GEMM for one batch: rows r and r+128
#define GEMM_ENC(bb) { \
    const ulonglong2* hp_ = (const ulonglong2*)h_s[bb]; \
    u64 a0_=0ull, a1_=0ull, d0_=0ull, d1_=0ull; \
    _Pragma("unroll") \
    for (int k_ = 0; k_ < 16; k_++){ \
        ulonglong2 hv_ = hp_[k_]; \
        a0_ = ffma2(hv_.x, wpA[2*k_],     a0_); \
        a1_ = ffma2(hv_.y, wpA[2*k_ + 1], a1_); \
        d0_ = ffma2(hv_.x, wpB[2*k_],     d0_); \
        d1_ = ffma2(hv_.y, wpB[2*k_ + 1], d1_); \
    } \
    float2 p_=unpk(a0_), q_=unpk(a1_), s_=unpk(d0_), w_=unpk(d1_); \
    g_s[bb][r]       = (p_.x+p_.y)+(q_.x+q_.y) + fmaf(wihA, xr[bb], biasA); \
    g_s[bb][r + 128] = (s_.x+s_.y)+(w_.x+w_.y) + fmaf(wihB, xr[bb], biasB); }

// decoder GEMM for one batch: rows r and r+128 (+65th h element)
#define GEMM_DEC(bb) { \
    const ulonglong2* hp_ = (const ulonglong2*)h_s[bb]; \
    u64 a0_=0ull, a1_=0ull, d0_=0ull, d1_=0ull; \
    _Pragma("unroll") \
    for (int k_ = 0; k_ < 16; k_++){ \
        ulonglong2 hv_ = hp_[k_]; \
        a0_ = ffma2(hv_.x, wpA[2*k_],     a0_); \
        a1_ = ffma2(hv_.y, wpA[2*k_ + 1], a1_); \
        d0_ = ffma2(hv_.x, wpB[2*k_],     d0_); \
        d1_ = ffma2(hv_.y, wpB[2*k_ + 1], d1_); \
    } \
    float hl_ = h_s[bb][HE]; \
    float2 p_=unpk(a0_), q_=unpk(a1_), s_=unpk(d0_), w_=unpk(d1_); \
    g_s[bb][r]       = (p_.x+p_.y)+(q_.x+q_.y) + fmaf(wlastA, hl_, fmaf(wihA, xr[bb], biasA)); \
    g_s[bb][r + 128] = (s_.x+s_.y)+(w_.x+w_.y) + fmaf(wlastB, hl_, fmaf(wihB, xr[bb], biasB)); }

// leftover decoder row: row 256+rr for batch bb
#define LEFTOVER(rr, bb) { \
    float acc_ = fmaf(wih_x[rr], xr[bb], b_x[rr]); \
    _Pragma("unroll") \
    for (int k_ = 0; k_ < HD; k_++) acc_ = fmaf(wx_s[rr][k_], h_s[bb][k_], acc_); \
    g_s[bb][GE + (rr)] = acc_; }

// output projection for batch bb at time tt
#define PROJ(bb, tt) { \
    float a0_=lb_, a1_=0.f, a2_=0.f, a3_=0.f; \
    _Pragma("unroll") \
    for (int k_ = 0; k_ < 64; k_ += 4){ \
        a0_ = fmaf(lw_s[k_  ], h_s[bb][k_  ], a0_); \
        a1_ = fmaf(lw_s[k_+1], h_s[bb][k_+1], a1_); \
        a2_ = fmaf(lw_s[k_+2], h_s[bb][k_+2], a2_); \
        a3_ = fmaf(lw_s[k_+3], h_s[bb][k_+3], a3_); \
    } \
    a0_ = fmaf(lw_s[64], h_s[bb][64], a0_); \
    out[(tt) * BTOT + b0 + (bb)] = (a0_ + a1_) + (a2_ + a3_); }

__global__ void __launch_bounds__(NTH, 2)
lstm_seq2seq_kernel(const float* __restrict__ input,   // (T,B,1)
                    const float* __restrict__ speed,   // (B,1)
                    const float* __restrict__ target,  // (T,B,1)
                    const float* __restrict__ eWih,    // (256,1)
                    const float* __restrict__ eWhh,    // (256,64)
                    const float* __restrict__ ebih,    // (256)
                    const float* __restrict__ ebhh,    // (256)
                    const float* __restrict__ dWih,    // (260,1)
                    const float* __restrict__ dWhh,    // (260,65)
                    const float* __restrict__ dbih,    // (260)
                    const float* __restrict__ dbhh,    // (260)
                    const float* __restrict__ linW,    // (1,65)
                    const float* __restrict__ linb,    // (1)
                    const float* __restrict__ denW,    // (1,1)
                    const float* __restrict__ denb,    // (1)
                    float* __restrict__ out)           // (T,B,1)
{
    __shared__ __align__(16) float h_s[NB][HSTR];
    __shared__ __align__(16) float g_s[NB][GD];
    __shared__ float x_s[2][NB];
    __shared__ __align__(16) float wx_s[4][HSTR];
    __shared__ float wih_x[4], b_x[4];
    __shared__ float lw_s[HD];
    __shared__ float sp_s[NB];

    const int tid  = threadIdx.x;
    const int lane = tid & 31;
    const int wrp  = tid >> 5;
    const int b0   = blockIdx.x * NB;
    const int r    = tid;              // thread owns gate rows r and r+128

    // ---------------- encoder weights: rows r and r+128 ----------------
    u64 wpA[32], wpB[32];
    {
        const ulonglong2* wrA = (const ulonglong2*)(eWhh + r * HE);
        const ulonglong2* wrB = (const ulonglong2*)(eWhh + (r + 128) * HE);
        #pragma unroll
        for (int j = 0; j < 16; j++){
            ulonglong2 va = wrA[j]; wpA[2*j] = va.x; wpA[2*j+1] = va.y;
            ulonglong2 vb = wrB[j]; wpB[2*j] = vb.x; wpB[2*j+1] = vb.y;
        }
    }
    float wihA  = eWih[r],           wihB  = eWih[r + 128];
    float biasA = ebih[r] + ebhh[r], biasB = ebih[r + 128] + ebhh[r + 128];

    for (int i = tid; i < NB * HSTR; i += NTH) ((float*)h_s)[i] = 0.0f;

    // encoder c state: G1 items {tid, tid+128}; G2 items {tid, tid+128(if tid<64)}
    float ce1[2] = {0.f, 0.f};
    float ce2[2] = {0.f, 0.f};

    const bool bvalid = (tid < NB) && (b0 + tid < BTOT);
    if (tid < NB) x_s[0][tid] = bvalid ? input[b0 + tid] : 0.0f;
    __syncthreads();

    // ================= encoder recurrence (G2 lags half a step) =================
    for (int t = 0; t < TS; t++){
        const float* xr = x_s[t & 1];
        float xnext = 0.0f;
        if (bvalid && t + 1 < TS) xnext = input[(t + 1) * BTOT + b0 + tid];

        // ---- phase 1: GEMM G1(t) + ACT G2(t-1) ----
        #pragma unroll
        for (int bb = 0; bb < NB1; bb++) GEMM_ENC(bb);
        if (t > 0){
            { int bb = 4 + (tid >> 6), uu = tid & 63; ACT_STEP(bb, uu, ce2[0], HE); }
            if (tid < 64){ int bb = 6, uu = tid;      ACT_STEP(bb, uu, ce2[1], HE); }
        }
        __syncthreads();

        // ---- phase 2: GEMM G2(t) + ACT G1(t) ----
        #pragma unroll
        for (int bb = NB1; bb < NB; bb++) GEMM_ENC(bb);
        { int bb = tid >> 6,         uu = tid & 63; ACT_STEP(bb, uu, ce1[0], HE); }
        { int bb = (tid + 128) >> 6, uu = tid & 63; ACT_STEP(bb, uu, ce1[1], HE); }
        if (tid < NB) x_s[(t + 1) & 1][tid] = xnext;
        __syncthreads();
    }
    // epilogue: drain ACT G2(TS-1)
    { int bb = 4 + (tid >> 6), uu = tid & 63; ACT_STEP(bb, uu, ce2[0], HE); }
    if (tid < 64){ int bb = 6, uu = tid;      ACT_STEP(bb, uu, ce2[1], HE); }
    __syncthreads();

    // ================= encoder -> decoder transition =================
    // park encoder c into g_s (uu < 64 region)
    g_s[tid >> 6][tid & 63]         = ce1[0];
    g_s[(tid + 128) >> 6][tid & 63] = ce1[1];
    g_s[4 + (tid >> 6)][tid & 63]   = ce2[0];
    if (tid < 64) g_s[6][tid]       = ce2[1];

    if (tid < NB){
        float sp = bvalid ? fmaf(speed[b0 + tid], denW[0], denb[0]) : 0.0f;
        sp_s[tid]     = sp;
        h_s[tid][HE]  = sp;     // 65th hidden element
        x_s[0][tid]   = 0.0f;   // teacher forcing: x_dec[0] = 0
    }
    if (tid < HD) lw_s[tid] = linW[tid];

    // decoder weights: rows r and r+128
    float wlastA, wlastB;
    {
        const float* wrA = dWhh + r * HD;
        const float* wrB = dWhh + (r + 128) * HD;
        #pragma unroll
        for (int j = 0; j < 32; j++){
            wpA[j] = pack2(wrA[2*j], wrA[2*j+1]);
            wpB[j] = pack2(wrB[2*j], wrB[2*j+1]);
        }
        wlastA = wrA[64]; wlastB = wrB[64];
    }
    wihA  = dWih[r];                 wihB  = dWih[r + 128];
    biasA = dbih[r] + dbhh[r];       biasB = dbih[r + 128] + dbhh[r + 128];

    if (tid < 4){
        const float* wr = dWhh + (GE + tid) * HD;
        for (int k = 0; k < HD; k++) wx_s[tid][k] = wr[k];
        wih_x[tid] = dWih[GE + tid];
        b_x[tid]   = dbih[GE + tid] + dbhh[GE + tid];
    }
    __syncthreads();

    // decoder activation item mappings (by group)
    // G1: batches 0..3, 260 items: {tid, tid+128, 256+tid(if tid<4)}
    int db1[3], du1[3]; float dc1[3];
    {
        int n0 = tid;        db1[0] = n0 / HD; du1[0] = n0 - db1[0] * HD;
        int n1 = tid + 128;  db1[1] = n1 / HD; du1[1] = n1 - db1[1] * HD;
        db1[2] = 3; du1[2] = 61 + (tid & 3);   // valid only tid < 4
        dc1[0] = (du1[0] < HE) ? g_s[db1[0]][du1[0]] : sp_s[db1[0]];
        dc1[1] = (du1[1] < HE) ? g_s[db1[1]][du1[1]] : sp_s[db1[1]];
        dc1[2] = (tid < 4) ? ((du1[2] < HE) ? g_s[3][du1[2]] : sp_s[3]) : 0.0f;
    }
    // G2: batches 4..6, 195 items: {tid, tid+128(if tid<67)}
    int db2[2], du2[2]; float dc2[2];
    {
        int m0 = tid;       int q0 = m0 / HD; db2[0] = 4 + q0; du2[0] = m0 - q0 * HD;
        int m1 = tid + 128; int q1 = m1 / HD; db2[1] = 4 + q1; du2[1] = m1 - q1 * HD;
        dc2[0] = (du2[0] < HE) ? g_s[db2[0]][du2[0]] : sp_s[db2[0]];
        dc2[1] = (tid < 67) ? ((du2[1] < HE) ? g_s[db2[1]][du2[1]] : sp_s[db2[1]]) : 0.0f;
    }
    float lb_ = linb[0];
    __syncthreads();   // c-init reads of g_s done before GEMM overwrites it

    // ================= decoder recurrence (G2 lags half a step) =================
    for (int t = 0; t < TS; t++){
        const float* xr = x_s[t & 1];
        float xnext = 0.0f;
        if (bvalid && t < TS - 1) xnext = target[t * BTOT + b0 + tid]; // x_dec[t+1]=target[t]

        // ---- phase 1: PROJ G1(t-1), GEMM G1(t), leftover G1, ACT G2(t-1) ----
        if (bvalid && tid < 4 && t > 0) PROJ(tid, t - 1);
        #pragma unroll
        for (int bb = 0; bb < NB1; bb++) GEMM_DEC(bb);
        if (lane < 4) LEFTOVER(wrp, lane);
        if (t > 0){
            ACT_STEP(db2[0], du2[0], dc2[0], HD);
            if (tid < 67) ACT_STEP(db2[1], du2[1], dc2[1], HD);
        }
        __syncthreads();

        // ---- phase 2: PROJ G2(t-1), GEMM G2(t), leftover G2, ACT G1(t) ----
        if (bvalid && tid >= 4 && t > 0) PROJ(tid, t - 1);
        #pragma unroll
        for (int bb = NB1; bb < NB; bb++) GEMM_DEC(bb);
        if (lane >= 4 && lane < NB) LEFTOVER(wrp, lane);
        ACT_STEP(db1[0], du1[0], dc1[0], HD);
        ACT_STEP(db1[1], du1[1], dc1[1], HD);
        if (tid < 4) ACT_STEP(db1[2], du1[2], dc1[2], HD);
        if (tid < NB) x_s[(t + 1) & 1][tid] = xnext;
        __syncthreads();
    }

    // epilogue: PROJ G1(TS-1), drain ACT G2(TS-1), then PROJ G2(TS-1)
    if (bvalid && tid < 4) PROJ(tid, TS - 1);
    ACT_STEP(db2[0], du2[0], dc2[0], HD);
    if (tid < 67) ACT_STEP(db2[1], du2[1], dc2[1], HD);
    __syncthreads();
    if (bvalid && tid >= 4) PROJ(tid, TS - 1);
}

extern "C" void kernel_launch(void* const* d_in, const int* in_sizes, int n_in,
                              void* d_out, int out_size)
{
    const float* input  = (const float*)d_in[0];
    const float* speed  = (const float*)d_in[1];
    const float* target = (const float*)d_in[2];
    const float* eWih   = (const float*)d_in[3];
    const float* eWhh   = (const float*)d_in[4];
    const float* ebih   = (const float*)d_in[5];
    const float* ebhh   = (const float*)d_in[6];
    const float* dWih   = (const float*)d_in[7];
    const float* dWhh   = (const float*)d_in[8];
    const float* dbih   = (const float*)d_in[9];
    const float* dbhh   = (const float*)d_in[10];
    const float* linW   = (const float*)d_in[11];
    const float* linb   = (const float*)d_in[12];
    const float* denW   = (const float*)d_in[13];
    const float* denb   = (const float*)d_in[14];
    float* outp = (float*)d_out;

    dim3 grid(NGRID);   // 296 blocks = 2 CTAs per SM
    dim3 block(NTH);    // 128 threads
    lstm_seq2seq_kernel<<<grid, block>>>(input, speed, target,
                                         eWih, eWhh, ebih, ebhh,
                                         dWih, dWhh, dbih, dbhh,
                                         linW, linb, denW, denb, outp);
}

// round 8
// speedup vs baseline: 1.0108x; 1.0108x over previous
#include <cuda_runtime.h>

// Problem constants
#define TS   1000
#define BTOT 2048
#define HE   64     // encoder hidden
#define HD   65     // decoder hidden
#define NB   14     // batch elements per block
#define NGRID 147   // ceil(2048/14)
#define NTH  256    // threads per block
#define HSTR 68     // h row stride (16B-aligned; 68%32=4 -> batch rows bank-distinct)
#define SCB  80     // scratch floats per batch row (80%32=16 -> conflict-free halves)
#define SCW  (7*SCB)

typedef unsigned long long u64;

__device__ __forceinline__ u64 pack2(float lo, float hi){
    u64 r; asm("mov.b64 %0, {%1, %2};" : "=l"(r) : "f"(lo), "f"(hi)); return r;
}
__device__ __forceinline__ float2 unpk(u64 v){
    float2 f; asm("mov.b64 {%0, %1}, %2;" : "=f"(f.x), "=f"(f.y) : "l"(v)); return f;
}
__device__ __forceinline__ u64 ffma2(u64 a, u64 b, u64 c){
    u64 d; asm("fma.rn.f32x2 %0, %1, %2, %3;" : "=l"(d) : "l"(a), "l"(b), "l"(c)); return d;
}
// accurate sigmoid (recurrent path: i, f gates)
__device__ __forceinline__ float sigf(float x){
    return __fdividef(1.0f, 1.0f + __expf(-x));
}
// accurate tanh (recurrent path: g gate)
__device__ __forceinline__ float tanhf_(float x){
    return fmaf(2.0f, sigf(2.0f * x), -1.0f);
}
// fast tanh via MUFU.TANH (non-recurrent path only)
__device__ __forceinline__ float tanha(float x){
    float y; asm("tanh.approx.f32 %0, %1;" : "=f"(y) : "f"(x)); return y;
}
// fast sigmoid via MUFU.TANH (o gate only)
__device__ __forceinline__ float siga(float x){
    return fmaf(0.5f, tanha(0.5f * x), 0.5f);
}

__global__ void __launch_bounds__(NTH, 1)
lstm_seq2seq_kernel(const float* __restrict__ input,   // (T,B,1)
                    const float* __restrict__ speed,   // (B,1)
                    const float* __restrict__ target,  // (T,B,1)
                    const float* __restrict__ eWih,    // (256,1)
                    const float* __restrict__ eWhh,    // (256,64)
                    const float* __restrict__ ebih,    // (256)
                    const float* __restrict__ ebhh,    // (256)
                    const float* __restrict__ dWih,    // (260,1)
                    const float* __restrict__ dWhh,    // (260,65)
                    const float* __restrict__ dbih,    // (260)
                    const float* __restrict__ dbhh,    // (260)
                    const float* __restrict__ linW,    // (1,65)
                    const float* __restrict__ linb,    // (1)
                    const float* __restrict__ denW,    // (1,1)
                    const float* __restrict__ denb,    // (1)
                    float* __restrict__ out)           // (T,B,1)
{
    __shared__ __align__(16) float hb[2][NB][HSTR];   // double-buffered hidden state
    __shared__ __align__(16) float sc[8 * SCW];       // per-warp gate scratch
    __shared__ __align__(16) float wx_s[4][HSTR];     // decoder unit-64 gate rows
    __shared__ __align__(16) float lw_s[HD + 3];      // output projection weights
    __shared__ float x_s[2][NB];
    __shared__ float sp_s[NB];
    __shared__ float wih_x[4], b_x[4];

    const int tid  = threadIdx.x;
    const int lane = tid & 31;
    const int w    = tid >> 5;         // warp 0..7
    const int bh   = w >> 2;           // batch half: batches bh*7 .. bh*7+6
    const int ub   = (w & 3) << 4;     // unit base (16 units per warp)
    const int lh   = lane & 15;        // unit offset within warp
    const int hi   = lane >> 4;        // 0: owns (i,f) rows, 1: owns (g,o) rows
    const int b0   = blockIdx.x * NB;
    float* scw = sc + w * SCW;
    const int offA = lh + (hi << 4);   // scratch slot: i(0-15) / g(16-31)
    const int offB = offA + 32;        //               f(32-47) / o(48-63)

    // ---------------- encoder weights: rows (i|g) and (f|o) of unit ub+lh ----------------
    const int erA = ub + lh + hi * 128;  // i-row u or g-row u+128
    const int erB = erA + 64;            // f-row u+64 or o-row u+192
    u64 wpA[32], wpB[32];
    {
        const ulonglong2* wrA = (const ulonglong2*)(eWhh + erA * HE);
        const ulonglong2* wrB = (const ulonglong2*)(eWhh + erB * HE);
        #pragma unroll
        for (int j = 0; j < 16; j++){
            ulonglong2 va = wrA[j]; wpA[2*j] = va.x; wpA[2*j+1] = va.y;
            ulonglong2 vb = wrB[j]; wpB[2*j] = vb.x; wpB[2*j+1] = vb.y;
        }
    }
    float wihA  = eWih[erA],             wihB  = eWih[erB];
    float biasA = ebih[erA] + ebhh[erA], biasB = ebih[erB] + ebhh[erB];

    // zero both h buffers
    for (int i = tid; i < 2 * NB * HSTR; i += NTH) ((float*)hb)[i] = 0.0f;

    // activation c state: item j -> (unit ub+(lane&15... via n), batch bh*7+bbl)
    float ce[4] = {0.f, 0.f, 0.f, 0.f};

    const bool bvalid = (tid < NB) && (b0 + tid < BTOT);
    if (tid < NB) x_s[0][tid] = bvalid ? input[b0 + tid] : 0.0f;
    __syncthreads();

    // ================= encoder recurrence: ONE barrier per step =================
    for (int t = 0; t < TS; t++){
        const int rb = t & 1;
        const float (*hr)[HSTR] = (const float (*)[HSTR])hb[rb];
        float (*hw)[HSTR] = hb[rb ^ 1];
        const float* xr = x_s[rb];
        float xnext = 0.0f;
        if (bvalid && t + 1 < TS) xnext = input[(t + 1) * BTOT + b0 + tid];

        // GEMM: 2 rows x 7 batches (broadcast h reads)
        float vA[7], vB[7];
        #pragma unroll
        for (int bb = 0; bb < 7; bb++){
            const int Bb = bh * 7 + bb;
            const ulonglong2* hp = (const ulonglong2*)hr[Bb];
            u64 a0=0ull, a1=0ull, d0=0ull, d1=0ull;
            #pragma unroll
            for (int k = 0; k < 16; k++){
                ulonglong2 hv = hp[k];
                a0 = ffma2(hv.x, wpA[2*k],   a0);
                a1 = ffma2(hv.y, wpA[2*k+1], a1);
                d0 = ffma2(hv.x, wpB[2*k],   d0);
                d1 = ffma2(hv.y, wpB[2*k+1], d1);
            }
            float2 p=unpk(a0), q=unpk(a1), s=unpk(d0), z=unpk(d1);
            vA[bb] = (p.x+p.y)+(q.x+q.y) + fmaf(wihA, xr[Bb], biasA);
            vB[bb] = (s.x+s.y)+(z.x+z.y) + fmaf(wihB, xr[Bb], biasB);
        }
        // warp-local gate exchange (no block barrier!)
        #pragma unroll
        for (int bb = 0; bb < 7; bb++){
            scw[bb*SCB + offA] = vA[bb];
            scw[bb*SCB + offB] = vB[bb];
        }
        __syncwarp();
        // packed activation (items: 16 units x 7 batches per warp)
        #pragma unroll
        for (int j = 0; j < 4; j++){
            int n = lane + 32*j;
            int bbl = n >> 4, uu = n & 15;
            if (j < 3 || hi == 0){
                float ii = scw[bbl*SCB      + uu];
                float gg = scw[bbl*SCB + 16 + uu];
                float ff = scw[bbl*SCB + 32 + uu];
                float oo = scw[bbl*SCB + 48 + uu];
                float cc = sigf(ff) * ce[j] + sigf(ii) * tanhf_(gg);
                ce[j] = cc;
                hw[bh*7 + bbl][ub + uu] = siga(oo) * tanha(cc);
            }
        }
        if (tid < NB) x_s[rb ^ 1][tid] = xnext;
        __syncthreads();
    }

    // ================= encoder -> decoder transition =================
    // encoder final h is in hb[0]; c carries over in ce (same item mapping!)
    if (tid < NB){
        float sp = bvalid ? fmaf(speed[b0 + tid], denW[0], denb[0]) : 0.0f;
        sp_s[tid] = sp;
        hb[0][tid][64] = sp;     // 65th hidden element of decoder initial state
        x_s[0][tid] = 0.0f;      // teacher forcing: x_dec[0] = 0
    }
    if (tid < HD) lw_s[tid] = linW[tid];
    if (tid < 4){
        const int r64 = 64 + 65 * tid;           // unit-64 gate rows: 64,129,194,259
        const float* wr = dWhh + r64 * HD;
        for (int k = 0; k < HD; k++) wx_s[tid][k] = wr[k];
        wih_x[tid] = dWih[r64];
        b_x[tid]   = dbih[r64] + dbhh[r64];
    }
    // decoder main rows for this thread
    const int drA = ub + lh + hi * 130;   // i-row u or g-row u+130
    const int drB = drA + 65;             // f-row u+65 or o-row u+195
    float wlastA, wlastB;
    {
        const float* wrA = dWhh + drA * HD;
        const float* wrB = dWhh + drB * HD;
        #pragma unroll
        for (int j = 0; j < 32; j++){
            wpA[j] = pack2(wrA[2*j], wrA[2*j+1]);
            wpB[j] = pack2(wrB[2*j], wrB[2*j+1]);
        }
        wlastA = wrA[64]; wlastB = wrB[64];
    }
    wihA  = dWih[drA];               wihB  = dWih[drB];
    biasA = dbih[drA] + dbhh[drA];   biasB = dbih[drB] + dbhh[drB];
    const float lb_ = linb[0];
    __syncthreads();

    // unit-64 assignment: warp quarter q handles batches 2q(,2q+1) of its half
    const int q    = w & 3;
    const int nb64 = (q == 3) ? 1 : 2;
    float c64 = 0.0f;
    if (hi == 1 && lh < nb64) c64 = sp_s[bh*7 + 2*q + lh];

    // ================= decoder recurrence: ONE barrier per step =================
    for (int t = 0; t < TS; t++){
        const int rb = t & 1;
        const float (*hr)[HSTR] = (const float (*)[HSTR])hb[rb];
        float (*hw)[HSTR] = hb[rb ^ 1];
        const float* xr = x_s[rb];
        float xnext = 0.0f;
        if (bvalid && t < TS - 1) xnext = target[t * BTOT + b0 + tid];

        // output projection of h(t-1) (lanes 30,31: 2 batches per warp)
        if (t > 0 && lane >= 30){
            int Bb = w + ((lane & 1) << 3);
            if (Bb < NB && b0 + Bb < BTOT){
                const float2* lp = (const float2*)lw_s;
                const float2* hp = (const float2*)hr[Bb];
                float s0 = lb_, s1 = 0.f;
                #pragma unroll
                for (int k = 0; k < 32; k++){
                    float2 a = lp[k], b = hp[k];
                    s0 = fmaf(a.x, b.x, s0);
                    s1 = fmaf(a.y, b.y, s1);
                }
                out[(t-1) * BTOT + b0 + Bb] = fmaf(lw_s[64], hr[Bb][64], s0 + s1);
            }
        }

        // main GEMM: 2 rows x 7 batches (+ 65th h element)
        float vA[7], vB[7];
        #pragma unroll
        for (int bb = 0; bb < 7; bb++){
            const int Bb = bh * 7 + bb;
            const ulonglong2* hp = (const ulonglong2*)hr[Bb];
            u64 a0=0ull, a1=0ull, d0=0ull, d1=0ull;
            #pragma unroll
            for (int k = 0; k < 16; k++){
                ulonglong2 hv = hp[k];
                a0 = ffma2(hv.x, wpA[2*k],   a0);
                a1 = ffma2(hv.y, wpA[2*k+1], a1);
                d0 = ffma2(hv.x, wpB[2*k],   d0);
                d1 = ffma2(hv.y, wpB[2*k+1], d1);
            }
            float hl = hr[Bb][64];
            float2 p=unpk(a0), q2=unpk(a1), s=unpk(d0), z=unpk(d1);
            vA[bb] = (p.x+p.y)+(q2.x+q2.y) + fmaf(wlastA, hl, fmaf(wihA, xr[Bb], biasA));
            vB[bb] = (s.x+s.y)+(z.x+z.y)   + fmaf(wlastB, hl, fmaf(wihB, xr[Bb], biasB));
        }
        // unit-64 gate rows (4*nb64 lanes per warp, float2 dots)
        float v64 = 0.0f;
        if (lane < 4 * nb64){
            const int g   = lane & 3;
            const int bbl = 2*q + (lane >> 2);
            const int Bb  = bh*7 + bbl;
            const float2* wp2 = (const float2*)wx_s[g];
            const float2* hp2 = (const float2*)hr[Bb];
            float s0 = 0.f, s1 = 0.f;
            #pragma unroll
            for (int k = 0; k < 32; k++){
                float2 a = wp2[k], b = hp2[k];
                s0 = fmaf(a.x, b.x, s0);
                s1 = fmaf(a.y, b.y, s1);
            }
            v64 = fmaf(wx_s[g][64], hr[Bb][64], s0 + s1) + fmaf(wih_x[g], xr[Bb], b_x[g]);
        }

        // warp-local gate exchange
        #pragma unroll
        for (int bb = 0; bb < 7; bb++){
            scw[bb*SCB + offA] = vA[bb];
            scw[bb*SCB + offB] = vB[bb];
        }
        if (lane < 4 * nb64)
            scw[(2*q + (lane >> 2))*SCB + 64 + (lane & 3)] = v64;
        __syncwarp();

        // packed activation, units 0..63
        #pragma unroll
        for (int j = 0; j < 4; j++){
            int n = lane + 32*j;
            int bbl = n >> 4, uu = n & 15;
            if (j < 3 || hi == 0){
                float ii = scw[bbl*SCB      + uu];
                float gg = scw[bbl*SCB + 16 + uu];
                float ff = scw[bbl*SCB + 32 + uu];
                float oo = scw[bbl*SCB + 48 + uu];
                float cc = sigf(ff) * ce[j] + sigf(ii) * tanhf_(gg);
                ce[j] = cc;
                hw[bh*7 + bbl][ub + uu] = siga(oo) * tanha(cc);
            }
        }
        // unit-64 activation (lanes 16..16+nb64-1)
        if (hi == 1 && lh < nb64){
            const int bbl = 2*q + lh;
            const int Bb  = bh*7 + bbl;
            float ii = scw[bbl*SCB + 64];
            float ff = scw[bbl*SCB + 65];
            float gg = scw[bbl*SCB + 66];
            float oo = scw[bbl*SCB + 67];
            float cc = sigf(ff) * c64 + sigf(ii) * tanhf_(gg);
            c64 = cc;
            hw[Bb][64] = siga(oo) * tanha(cc);
        }
        if (tid < NB) x_s[rb ^ 1][tid] = xnext;
        __syncthreads();
    }

    // final output projection: h(TS) is in hb[0]
    if (lane >= 30){
        int Bb = w + ((lane & 1) << 3);
        if (Bb < NB && b0 + Bb < BTOT){
            const float2* lp = (const float2*)lw_s;
            const float2* hp = (const float2*)hb[0][Bb];
            float s0 = lb_, s1 = 0.f;
            #pragma unroll
            for (int k = 0; k < 32; k++){
                float2 a = lp[k], b = hp[k];
                s0 = fmaf(a.x, b.x, s0);
                s1 = fmaf(a.y, b.y, s1);
            }
            out[(TS-1) * BTOT + b0 + Bb] = fmaf(lw_s[64], hb[0][Bb][64], s0 + s1);
        }
    }
}

extern "C" void kernel_launch(void* const* d_in, const int* in_sizes, int n_in,
                              void* d_out, int out_size)
{
    const float* input  = (const float*)d_in[0];
    const float* speed  = (const float*)d_in[1];
    const float* target = (const float*)d_in[2];
    const float* eWih   = (const float*)d_in[3];
    const float* eWhh   = (const float*)d_in[4];
    const float* ebih   = (const float*)d_in[5];
    const float* ebhh   = (const float*)d_in[6];
    const float* dWih   = (const float*)d_in[7];
    const float* dWhh   = (const float*)d_in[8];
    const float* dbih   = (const float*)d_in[9];
    const float* dbhh   = (const float*)d_in[10];
    const float* linW   = (const float*)d_in[11];
    const float* linb   = (const float*)d_in[12];
    const float* denW   = (const float*)d_in[13];
    const float* denb   = (const float*)d_in[14];
    float* outp = (float*)d_out;

    dim3 grid(NGRID);   // 147 blocks, 1 per SM, single wave
    dim3 block(NTH);    // 256 threads
    lstm_seq2seq_kernel<<<grid, block>>>(input, speed, target,
                                         eWih, eWhh, ebih, ebhh,
                                         dWih, dWhh, dbih, dbhh,
                                         linW, linb, denW, denb, outp);
}

// round 9
// speedup vs baseline: 1.1643x; 1.1519x over previous
#include <cuda_runtime.h>

// Problem constants
#define TS   1000
#define BTOT 2048
#define HE   64     // encoder hidden
#define HD   65     // decoder hidden
#define NB   14     // batch elements per block (two groups of 7)
#define NGRID 147   // ceil(2048/14)
#define NTH  256    // threads per block
#define HSTR 68     // h row stride
#define SCB  80     // scratch floats per batch row (conflict-free halves)
#define SCW  (7*SCB)

typedef unsigned long long u64;

__device__ __forceinline__ u64 pack2(float lo, float hi){
    u64 r; asm("mov.b64 %0, {%1, %2};" : "=l"(r) : "f"(lo), "f"(hi)); return r;
}
__device__ __forceinline__ float2 unpk(u64 v){
    float2 f; asm("mov.b64 {%0, %1}, %2;" : "=f"(f.x), "=f"(f.y) : "l"(v)); return f;
}
__device__ __forceinline__ u64 ffma2(u64 a, u64 b, u64 c){
    u64 d; asm("fma.rn.f32x2 %0, %1, %2, %3;" : "=l"(d) : "l"(a), "l"(b), "l"(c)); return d;
}
// fast tanh via MUFU.TANH (measured contribution to final rel_err ~1e-6)
__device__ __forceinline__ float tanha(float x){
    float y; asm("tanh.approx.f32 %0, %1;" : "=f"(y) : "f"(x)); return y;
}
// fast sigmoid via MUFU.TANH
__device__ __forceinline__ float siga(float x){
    return fmaf(0.5f, tanha(0.5f * x), 0.5f);
}

// group-scoped named barrier (group 0 -> id 1, group 1 -> id 2)
#define GBAR() asm volatile("bar.sync %0, %1;" :: "r"(grp + 1), "r"(128) : "memory")

__global__ void __launch_bounds__(NTH, 1)
lstm_seq2seq_kernel(const float* __restrict__ input,   // (T,B,1)
                    const float* __restrict__ speed,   // (B,1)
                    const float* __restrict__ target,  // (T,B,1)
                    const float* __restrict__ eWih,    // (256,1)
                    const float* __restrict__ eWhh,    // (256,64)
                    const float* __restrict__ ebih,    // (256)
                    const float* __restrict__ ebhh,    // (256)
                    const float* __restrict__ dWih,    // (260,1)
                    const float* __restrict__ dWhh,    // (260,65)
                    const float* __restrict__ dbih,    // (260)
                    const float* __restrict__ dbhh,    // (260)
                    const float* __restrict__ linW,    // (1,65)
                    const float* __restrict__ linb,    // (1)
                    const float* __restrict__ denW,    // (1,1)
                    const float* __restrict__ denb,    // (1)
                    float* __restrict__ out)           // (T,B,1)
{
    __shared__ __align__(16) float hb[2][NB][HSTR];   // double-buffered hidden state
    __shared__ __align__(16) float sc[8 * SCW];       // per-warp gate scratch
    __shared__ __align__(16) float wx_s[4][HSTR];     // decoder unit-64 gate rows
    __shared__ __align__(16) float lw_s[HD + 3];      // output projection weights
    __shared__ float x_s[2][NB];
    __shared__ float sp_s[NB];
    __shared__ float wih_x[4], b_x[4];

    const int tid  = threadIdx.x;
    const int lane = tid & 31;
    const int w    = tid >> 5;         // warp 0..7
    const int grp  = w >> 2;           // group 0: warps 0-3 / batches 0-6; group 1: warps 4-7 / 7-13
    const int gtid = tid & 127;        // thread id within group
    const int ub   = (w & 3) << 4;     // unit base (16 units per warp)
    const int lh   = lane & 15;        // unit offset within warp
    const int hi   = lane >> 4;        // 0: owns (i,f) rows, 1: owns (g,o) rows
    const int b0   = blockIdx.x * NB;
    float* scw = sc + w * SCW;
    const int offA = lh + (hi << 4);   // scratch slot: i(0-15) / g(16-31)
    const int offB = offA + 32;        //               f(32-47) / o(48-63)

    // per-group x loader role: thread gtid<7 loads batch grp*7+gtid
    const int  xb     = grp * 7 + gtid;                 // meaningful for gtid<7
    const bool xload  = (gtid < 7);
    const bool xvalid = xload && (b0 + xb < BTOT);

    // ---------------- encoder weights: rows (i|g) and (f|o) of unit ub+lh ----------------
    const int erA = ub + lh + hi * 128;  // i-row u or g-row u+128
    const int erB = erA + 64;            // f-row u+64 or o-row u+192
    u64 wpA[32], wpB[32];
    {
        const ulonglong2* wrA = (const ulonglong2*)(eWhh + erA * HE);
        const ulonglong2* wrB = (const ulonglong2*)(eWhh + erB * HE);
        #pragma unroll
        for (int j = 0; j < 16; j++){
            ulonglong2 va = wrA[j]; wpA[2*j] = va.x; wpA[2*j+1] = va.y;
            ulonglong2 vb = wrB[j]; wpB[2*j] = vb.x; wpB[2*j+1] = vb.y;
        }
    }
    float wihA  = eWih[erA],             wihB  = eWih[erB];
    float biasA = ebih[erA] + ebhh[erA], biasB = ebih[erB] + ebhh[erB];

    // zero both h buffers
    for (int i = tid; i < 2 * NB * HSTR; i += NTH) ((float*)hb)[i] = 0.0f;

    float ce[4] = {0.f, 0.f, 0.f, 0.f};

    if (tid < NB) x_s[0][tid] = (b0 + tid < BTOT) ? input[b0 + tid] : 0.0f;
    __syncthreads();

    // ================= encoder recurrence: ONE group barrier per step =================
    for (int t = 0; t < TS; t++){
        const int rb = t & 1;
        const float (*hr)[HSTR] = (const float (*)[HSTR])hb[rb];
        float (*hw)[HSTR] = hb[rb ^ 1];
        const float* xr = x_s[rb];
        float xnext = 0.0f;
        if (xvalid && t + 1 < TS) xnext = input[(t + 1) * BTOT + b0 + xb];

        // GEMM: 2 rows x 7 batches (broadcast h reads)
        float vA[7], vB[7];
        #pragma unroll
        for (int bb = 0; bb < 7; bb++){
            const int Bb = grp * 7 + bb;
            const ulonglong2* hp = (const ulonglong2*)hr[Bb];
            u64 a0=0ull, a1=0ull, d0=0ull, d1=0ull;
            #pragma unroll
            for (int k = 0; k < 16; k++){
                ulonglong2 hv = hp[k];
                a0 = ffma2(hv.x, wpA[2*k],   a0);
                a1 = ffma2(hv.y, wpA[2*k+1], a1);
                d0 = ffma2(hv.x, wpB[2*k],   d0);
                d1 = ffma2(hv.y, wpB[2*k+1], d1);
            }
            float2 p=unpk(a0), q=unpk(a1), s=unpk(d0), z=unpk(d1);
            vA[bb] = (p.x+p.y)+(q.x+q.y) + fmaf(wihA, xr[Bb], biasA);
            vB[bb] = (s.x+s.y)+(z.x+z.y) + fmaf(wihB, xr[Bb], biasB);
        }
        // warp-local gate exchange
        #pragma unroll
        for (int bb = 0; bb < 7; bb++){
            scw[bb*SCB + offA] = vA[bb];
            scw[bb*SCB + offB] = vB[bb];
        }
        __syncwarp();
        // packed activation (items: 16 units x 7 batches per warp)
        #pragma unroll
        for (int j = 0; j < 4; j++){
            int n = lane + 32*j;
            int bbl = n >> 4, uu = n & 15;
            if (j < 3 || hi == 0){
                float ii = scw[bbl*SCB      + uu];
                float gg = scw[bbl*SCB + 16 + uu];
                float ff = scw[bbl*SCB + 32 + uu];
                float oo = scw[bbl*SCB + 48 + uu];
                float cc = siga(ff) * ce[j] + siga(ii) * tanha(gg);
                ce[j] = cc;
                hw[grp*7 + bbl][ub + uu] = siga(oo) * tanha(cc);
            }
        }
        if (xload) x_s[rb ^ 1][xb] = xnext;
        GBAR();
    }

    // ================= encoder -> decoder transition (block-wide, once) =================
    __syncthreads();   // re-join groups before touching shared transition state
    if (tid < NB){
        float sp = (b0 + tid < BTOT) ? fmaf(speed[b0 + tid], denW[0], denb[0]) : 0.0f;
        sp_s[tid] = sp;
        hb[0][tid][64] = sp;     // 65th hidden element of decoder initial state
        x_s[0][tid] = 0.0f;      // teacher forcing: x_dec[0] = 0
    }
    if (tid < HD) lw_s[tid] = linW[tid];
    if (tid < 4){
        const int r64 = 64 + 65 * tid;           // unit-64 gate rows: 64,129,194,259
        const float* wr = dWhh + r64 * HD;
        for (int k = 0; k < HD; k++) wx_s[tid][k] = wr[k];
        wih_x[tid] = dWih[r64];
        b_x[tid]   = dbih[r64] + dbhh[r64];
    }
    // decoder main rows for this thread
    const int drA = ub + lh + hi * 130;   // i-row u or g-row u+130
    const int drB = drA + 65;             // f-row u+65 or o-row u+195
    float wlastA, wlastB;
    {
        const float* wrA = dWhh + drA * HD;
        const float* wrB = dWhh + drB * HD;
        #pragma unroll
        for (int j = 0; j < 32; j++){
            wpA[j] = pack2(wrA[2*j], wrA[2*j+1]);
            wpB[j] = pack2(wrB[2*j], wrB[2*j+1]);
        }
        wlastA = wrA[64]; wlastB = wrB[64];
    }
    wihA  = dWih[drA];               wihB  = dWih[drB];
    biasA = dbih[drA] + dbhh[drA];   biasB = dbih[drB] + dbhh[drB];
    const float lb_ = linb[0];
    __syncthreads();

    // unit-64 assignment: warp quarter q handles local batches 2q(,2q+1) of its group
    const int q    = w & 3;
    const int nb64 = (q == 3) ? 1 : 2;
    float c64 = 0.0f;
    if (hi == 1 && lh < nb64) c64 = sp_s[grp*7 + 2*q + lh];

    // ================= decoder recurrence: ONE group barrier per step =================
    for (int t = 0; t < TS; t++){
        const int rb = t & 1;
        const float (*hr)[HSTR] = (const float (*)[HSTR])hb[rb];
        float (*hw)[HSTR] = hb[rb ^ 1];
        const float* xr = x_s[rb];
        float xnext = 0.0f;
        if (xvalid && t < TS - 1) xnext = target[t * BTOT + b0 + xb];

        // output projection of h(t-1) (lanes 30,31: up to 2 local batches per warp)
        if (t > 0 && lane >= 30){
            int bl = 2*q + (lane & 1);
            if (bl < 7){
                int Bb = grp*7 + bl;
                if (b0 + Bb < BTOT){
                    const float2* lp = (const float2*)lw_s;
                    const float2* hp = (const float2*)hr[Bb];
                    float s0 = lb_, s1 = 0.f;
                    #pragma unroll
                    for (int k = 0; k < 32; k++){
                        float2 a = lp[k], b = hp[k];
                        s0 = fmaf(a.x, b.x, s0);
                        s1 = fmaf(a.y, b.y, s1);
                    }
                    out[(t-1) * BTOT + b0 + Bb] = fmaf(lw_s[64], hr[Bb][64], s0 + s1);
                }
            }
        }

        // main GEMM: 2 rows x 7 batches (+ 65th h element)
        float vA[7], vB[7];
        #pragma unroll
        for (int bb = 0; bb < 7; bb++){
            const int Bb = grp * 7 + bb;
            const ulonglong2* hp = (const ulonglong2*)hr[Bb];
            u64 a0=0ull, a1=0ull, d0=0ull, d1=0ull;
            #pragma unroll
            for (int k = 0; k < 16; k++){
                ulonglong2 hv = hp[k];
                a0 = ffma2(hv.x, wpA[2*k],   a0);
                a1 = ffma2(hv.y, wpA[2*k+1], a1);
                d0 = ffma2(hv.x, wpB[2*k],   d0);
                d1 = ffma2(hv.y, wpB[2*k+1], d1);
            }
            float hl = hr[Bb][64];
            float2 p=unpk(a0), q2=unpk(a1), s=unpk(d0), z=unpk(d1);
            vA[bb] = (p.x+p.y)+(q2.x+q2.y) + fmaf(wlastA, hl, fmaf(wihA, xr[Bb], biasA));
            vB[bb] = (s.x+s.y)+(z.x+z.y)   + fmaf(wlastB, hl, fmaf(wihB, xr[Bb], biasB));
        }
        // unit-64 gate rows (4*nb64 lanes per warp, float2 dots)
        float v64 = 0.0f;
        if (lane < 4 * nb64){
            const int g   = lane & 3;
            const int bbl = 2*q + (lane >> 2);
            const int Bb  = grp*7 + bbl;
            const float2* wp2 = (const float2*)wx_s[g];
            const float2* hp2 = (const float2*)hr[Bb];
            float s0 = 0.f, s1 = 0.f;
            #pragma unroll
            for (int k = 0; k < 32; k++){
                float2 a = wp2[k], b = hp2[k];
                s0 = fmaf(a.x, b.x, s0);
                s1 = fmaf(a.y, b.y, s1);
            }
            v64 = fmaf(wx_s[g][64], hr[Bb][64], s0 + s1) + fmaf(wih_x[g], xr[Bb], b_x[g]);
        }

        // warp-local gate exchange
        #pragma unroll
        for (int bb = 0; bb < 7; bb++){
            scw[bb*SCB + offA] = vA[bb];
            scw[bb*SCB + offB] = vB[bb];
        }
        if (lane < 4 * nb64)
            scw[(2*q + (lane >> 2))*SCB + 64 + (lane & 3)] = v64;
        __syncwarp();

        // packed activation, units 0..63
        #pragma unroll
        for (int j = 0; j < 4; j++){
            int n = lane + 32*j;
            int bbl = n >> 4, uu = n & 15;
            if (j < 3 || hi == 0){
                float ii = scw[bbl*SCB      + uu];
                float gg = scw[bbl*SCB + 16 + uu];
                float ff = scw[bbl*SCB + 32 + uu];
                float oo = scw[bbl*SCB + 48 + uu];
                float cc = siga(ff) * ce[j] + siga(ii) * tanha(gg);
                ce[j] = cc;
                hw[grp*7 + bbl][ub + uu] = siga(oo) * tanha(cc);
            }
        }
        // unit-64 activation (lanes 16..16+nb64-1)
        if (hi == 1 && lh < nb64){
            const int bbl = 2*q + lh;
            const int Bb  = grp*7 + bbl;
            float ii = scw[bbl*SCB + 64];
            float ff = scw[bbl*SCB + 65];
            float gg = scw[bbl*SCB + 66];
            float oo = scw[bbl*SCB + 67];
            float cc = siga(ff) * c64 + siga(ii) * tanha(gg);
            c64 = cc;
            hw[Bb][64] = siga(oo) * tanha(cc);
        }
        if (xload) x_s[rb ^ 1][xb] = xnext;
        GBAR();
    }

    // final output projection: h(TS) is in hb[0]
    if (lane >= 30){
        int bl = 2*q + (lane & 1);
        if (bl < 7){
            int Bb = grp*7 + bl;
            if (b0 + Bb < BTOT){
                const float2* lp = (const float2*)lw_s;
                const float2* hp = (const float2*)hb[0][Bb];
                float s0 = lb_, s1 = 0.f;
                #pragma unroll
                for (int k = 0; k < 32; k++){
                    float2 a = lp[k], b = hp[k];
                    s0 = fmaf(a.x, b.x, s0);
                    s1 = fmaf(a.y, b.y, s1);
                }
                out[(TS-1) * BTOT + b0 + Bb] = fmaf(lw_s[64], hb[0][Bb][64], s0 + s1);
            }
        }
    }
}

extern "C" void kernel_launch(void* const* d_in, const int* in_sizes, int n_in,
                              void* d_out, int out_size)
{
    const float* input  = (const float*)d_in[0];
    const float* speed  = (const float*)d_in[1];
    const float* target = (const float*)d_in[2];
    const float* eWih   = (const float*)d_in[3];
    const float* eWhh   = (const float*)d_in[4];
    const float* ebih   = (const float*)d_in[5];
    const float* ebhh   = (const float*)d_in[6];
    const float* dWih   = (const float*)d_in[7];
    const float* dWhh   = (const float*)d_in[8];
    const float* dbih   = (const float*)d_in[9];
    const float* dbhh   = (const float*)d_in[10];
    const float* linW   = (const float*)d_in[11];
    const float* linb   = (const float*)d_in[12];
    const float* denW   = (const float*)d_in[13];
    const float* denb   = (const float*)d_in[14];
    float* outp = (float*)d_out;

    dim3 grid(NGRID);   // 147 blocks, 1 per SM
    dim3 block(NTH);    // 256 threads = two independent 128-thread groups
    lstm_seq2seq_kernel<<<grid, block>>>(input, speed, target,
                                         eWih, eWhh, ebih, ebhh,
                                         dWih, dWhh, dbih, dbhh,
                                         linW, linb, denW, denb, outp);
}